// round 3
// baseline (speedup 1.0000x reference)
#include <cuda_runtime.h>
#include <math.h>

// Fixed problem shapes
#define BB 16
#define HH 256
#define WW 256
#define SS 24
#define PS (HH * WW)             // per-channel plane stride
#define NPIX (BB * HH * WW)      // 1,048,576
#define NBLK 1024                // blocks: 4 rows per block
#define EPSF 1e-6f
#define WGRAD 0.05f

typedef unsigned long long ull;

__device__ float2 g_partials[NBLK];
__device__ unsigned int g_count = 0;

// ---------- packed f32x2 + MUFU helpers ----------
__device__ __forceinline__ ull pack2(float lo, float hi) {
    ull r; asm("mov.b64 %0, {%1, %2};" : "=l"(r) : "f"(lo), "f"(hi)); return r;
}
__device__ __forceinline__ void unpack2(ull v, float& lo, float& hi) {
    asm("mov.b64 {%0, %1}, %2;" : "=f"(lo), "=f"(hi) : "l"(v));
}
__device__ __forceinline__ ull fma2(ull a, ull b, ull c) {
    ull r; asm("fma.rn.f32x2 %0, %1, %2, %3;" : "=l"(r) : "l"(a), "l"(b), "l"(c)); return r;
}
__device__ __forceinline__ ull mul2(ull a, ull b) {
    ull r; asm("mul.rn.f32x2 %0, %1, %2;" : "=l"(r) : "l"(a), "l"(b)); return r;
}
__device__ __forceinline__ float sqrta(float x) {
    float r; asm("sqrt.approx.f32 %0, %1;" : "=f"(r) : "f"(x)); return r;
}
__device__ __forceinline__ float rsqrta(float x) {
    float r; asm("rsqrt.approx.f32 %0, %1;" : "=f"(r) : "f"(x)); return r;
}

// acos on [0,1]: deg-7 minimax (A&S 4.4.46 family), abs err ~2e-8
__device__ __forceinline__ float acos_fast(float x) {
    float p = fmaf(x, -0.0012624911f, 0.0066700901f);
    p = fmaf(x, p, -0.0170881256f);
    p = fmaf(x, p,  0.0308918810f);
    p = fmaf(x, p, -0.0501743046f);
    p = fmaf(x, p,  0.0889789874f);
    p = fmaf(x, p, -0.2145988016f);
    p = fmaf(x, p,  1.5707963050f);
    return sqrta(1.0f - x) * p;
}

// one pixel's gradient-magnitude L1 contribution (raw, unnormalized quats)
__device__ __forceinline__ float grad_term(float pc, float pr, float pd,
                                           float tc, float tr, float td) {
    float gxp = pr - pc, gyp = pd - pc;
    float gxt = tr - tc, gyt = td - tc;
    float gp = sqrta(fmaf(gxp, gxp, fmaf(gyp, gyp, EPSF)));
    float gt = sqrta(fmaf(gxt, gxt, fmaf(gyt, gyt, EPSF)));
    return fabsf(gp - gt);
}

__global__ __launch_bounds__(256, 4) void fused_loss_kernel(
    const float* __restrict__ qp,
    const float* __restrict__ qt,
    const float* __restrict__ syms,
    float* __restrict__ out)
{
    // Sign-adjusted symmetry splats, packed 2-wide: s2[s] = { {a,a},{b,b} }, { {c,c},{d,d} }
    __shared__ ulonglong2 s2[SS][2];
    __shared__ float2 wsum[8];
    __shared__ bool amLast;

    const int tid = threadIdx.x;
    if (tid < SS) {
        float a =  syms[tid * 4 + 0];
        float b = -syms[tid * 4 + 1];
        float c = -syms[tid * 4 + 2];
        float d = -syms[tid * 4 + 3];
        s2[tid][0] = make_ulonglong2(pack2(a, a), pack2(b, b));
        s2[tid][1] = make_ulonglong2(pack2(c, c), pack2(d, d));
    }
    __syncthreads();

    // 4 rows per block, 64 threads per row, 4 pixels per thread (float4)
    const int row = (blockIdx.x << 2) + (tid >> 6);   // row = b*HH + h
    const int t   = tid & 63;
    const int b   = row >> 8;
    const int h   = row & (HH - 1);
    const int base = b * 4 * PS + h * WW + (t << 2);
    const int dh  = (h < HH - 1) ? WW : -WW;          // mirrored edge: |diff| identical
    const bool hasr = (t < 63);

    // ---- per-channel: load + gradient term (neighbors are transient) ----
    float4 P[4], T[4];
    float gsum = 0.0f;
#pragma unroll
    for (int c = 0; c < 4; c++) {
        const float* pp = qp + base + c * PS;
        const float* tt = qt + base + c * PS;
        float4 p  = __ldg((const float4*)pp);
        float4 tq = __ldg((const float4*)tt);
        float4 pd = __ldg((const float4*)(pp + dh));
        float4 td = __ldg((const float4*)(tt + dh));
        float pr3 = hasr ? __ldg(pp + 4) : p.z;   // mirrored right edge
        float tr3 = hasr ? __ldg(tt + 4) : tq.z;

        gsum += grad_term(p.x, p.y, pd.x, tq.x, tq.y, td.x);
        gsum += grad_term(p.y, p.z, pd.y, tq.y, tq.z, td.y);
        gsum += grad_term(p.z, p.w, pd.z, tq.z, tq.w, td.z);
        gsum += grad_term(p.w, pr3, pd.w, tq.w, tr3, td.w);

        P[c] = p; T[c] = tq;
    }

    // ---- per-pixel: normalize + relative quaternion ----
    float rw[4], rx[4], ry[4], rz[4];
#pragma unroll
    for (int i = 0; i < 4; i++) {
        float pv0 = ((const float*)&P[0])[i], pv1 = ((const float*)&P[1])[i];
        float pv2 = ((const float*)&P[2])[i], pv3 = ((const float*)&P[3])[i];
        float tv0 = ((const float*)&T[0])[i], tv1 = ((const float*)&T[1])[i];
        float tv2 = ((const float*)&T[2])[i], tv3 = ((const float*)&T[3])[i];

        float dp = fmaf(pv0, pv0, fmaf(pv1, pv1, fmaf(pv2, pv2, pv3*pv3)));
        float dt = fmaf(tv0, tv0, fmaf(tv1, tv1, fmaf(tv2, tv2, tv3*tv3)));
        float ip = rsqrta(dp);
        float it = rsqrta(dt);
        float w1 = pv0*ip, x1 = pv1*ip, y1 = pv2*ip, z1 = pv3*ip;
        float w2 = tv0*it, x2 = tv1*it, y2 = tv2*it, z2 = tv3*it;
        rw[i] =  w2*w1 + x2*x1 + y2*y1 + z2*z1;
        rx[i] = -w2*x1 + x2*w1 - y2*z1 + z2*y1;
        ry[i] = -w2*y1 + x2*z1 + y2*w1 - z2*x1;
        rz[i] = -w2*z1 - x2*y1 + y2*x1 + z2*w1;
    }

    // ---- 24-symmetry max|dot| on packed f32x2 (2 pixels per op) ----
    ull rw01 = pack2(rw[0], rw[1]), rw23 = pack2(rw[2], rw[3]);
    ull rx01 = pack2(rx[0], rx[1]), rx23 = pack2(rx[2], rx[3]);
    ull ry01 = pack2(ry[0], ry[1]), ry23 = pack2(ry[2], ry[3]);
    ull rz01 = pack2(rz[0], rz[1]), rz23 = pack2(rz[2], rz[3]);
    const ull ABS2 = 0x7FFFFFFF7FFFFFFFULL;
    float m0 = 0.0f, m1 = 0.0f, m2 = 0.0f, m3 = 0.0f;
#pragma unroll
    for (int s = 0; s < SS; s++) {
        ulonglong2 vab = s2[s][0];   // {x,x}, {y,y}
        ulonglong2 vcd = s2[s][1];   // {z,z}, {w,w}
        ull d01 = fma2(rw01, vab.x, fma2(rx01, vab.y, fma2(ry01, vcd.x, mul2(rz01, vcd.y)))) & ABS2;
        ull d23 = fma2(rw23, vab.x, fma2(rx23, vab.y, fma2(ry23, vcd.x, mul2(rz23, vcd.y)))) & ABS2;
        float a, bb;
        unpack2(d01, a, bb); m0 = fmaxf(m0, a); m1 = fmaxf(m1, bb);
        unpack2(d23, a, bb); m2 = fmaxf(m2, a); m3 = fmaxf(m3, bb);
    }
    const float CL = 1.0f - EPSF;
    float rot = acos_fast(fminf(m0, CL)) + acos_fast(fminf(m1, CL))
              + acos_fast(fminf(m2, CL)) + acos_fast(fminf(m3, CL));
    rot *= 2.0f;

    // ---- block reduction ----
    float r = rot, g = gsum;
#pragma unroll
    for (int o = 16; o > 0; o >>= 1) {
        r += __shfl_xor_sync(0xFFFFFFFFu, r, o);
        g += __shfl_xor_sync(0xFFFFFFFFu, g, o);
    }
    const int lane = tid & 31;
    const int warp = tid >> 5;
    if (lane == 0) wsum[warp] = make_float2(r, g);
    __syncthreads();
    if (warp == 0) {
        float2 v = (lane < 8) ? wsum[lane] : make_float2(0.0f, 0.0f);
        float rr = v.x, gg = v.y;
#pragma unroll
        for (int o = 4; o > 0; o >>= 1) {
            rr += __shfl_xor_sync(0xFFFFFFFFu, rr, o);
            gg += __shfl_xor_sync(0xFFFFFFFFu, gg, o);
        }
        if (lane == 0) {
            g_partials[blockIdx.x] = make_float2(rr, gg);
            __threadfence();
            unsigned int c = atomicAdd(&g_count, 1u);
            amLast = (c == NBLK - 1);
        }
    }
    __syncthreads();

    // ---- last block: grid-wide finish (deterministic fixed-order sum) ----
    if (amLast) {
        float r2 = 0.0f, g2 = 0.0f;
#pragma unroll
        for (int i = tid; i < NBLK; i += 256) {
            float2 v = __ldcg(&g_partials[i]);
            r2 += v.x; g2 += v.y;
        }
#pragma unroll
        for (int o = 16; o > 0; o >>= 1) {
            r2 += __shfl_xor_sync(0xFFFFFFFFu, r2, o);
            g2 += __shfl_xor_sync(0xFFFFFFFFu, g2, o);
        }
        if (lane == 0) wsum[warp] = make_float2(r2, g2);
        __syncthreads();
        if (tid == 0) {
            float rr = 0.0f, gg = 0.0f;
#pragma unroll
            for (int i = 0; i < 8; i++) { rr += wsum[i].x; gg += wsum[i].y; }
            out[0] = rr / (float)NPIX + WGRAD * (gg / (float)(4 * NPIX));
            g_count = 0;   // reset for next graph replay
        }
    }
}

extern "C" void kernel_launch(void* const* d_in, const int* in_sizes, int n_in,
                              void* d_out, int out_size)
{
    const float* qp   = (const float*)d_in[0];
    const float* qt   = (const float*)d_in[1];
    const float* syms = (const float*)d_in[2];
    float* out = (float*)d_out;

    fused_loss_kernel<<<NBLK, 256>>>(qp, qt, syms, out);
}

// round 4
// speedup vs baseline: 1.0019x; 1.0019x over previous
#include <cuda_runtime.h>
#include <math.h>

// Fixed problem shapes
#define BB 16
#define HH 256
#define WW 256
#define SS 24
#define PS (HH * WW)             // per-channel plane stride
#define NPIX (BB * HH * WW)      // 1,048,576
#define NBLK 1024                // blocks: 4 rows per block
#define EPSF 1e-6f
#define WGRAD 0.05f

typedef unsigned long long ull;

__device__ float2 g_partials[NBLK];
__device__ unsigned int g_count = 0;

// ---------- packed f32x2 + MUFU helpers ----------
__device__ __forceinline__ ull pack2(float lo, float hi) {
    ull r; asm("mov.b64 %0, {%1, %2};" : "=l"(r) : "f"(lo), "f"(hi)); return r;
}
__device__ __forceinline__ void unpack2(ull v, float& lo, float& hi) {
    asm("mov.b64 {%0, %1}, %2;" : "=f"(lo), "=f"(hi) : "l"(v));
}
__device__ __forceinline__ ull fma2(ull a, ull b, ull c) {
    ull r; asm("fma.rn.f32x2 %0, %1, %2, %3;" : "=l"(r) : "l"(a), "l"(b), "l"(c)); return r;
}
__device__ __forceinline__ ull mul2(ull a, ull b) {
    ull r; asm("mul.rn.f32x2 %0, %1, %2;" : "=l"(r) : "l"(a), "l"(b)); return r;
}
__device__ __forceinline__ float sqrta(float x) {
    float r; asm("sqrt.approx.f32 %0, %1;" : "=f"(r) : "f"(x)); return r;
}
__device__ __forceinline__ float rsqrta(float x) {
    float r; asm("rsqrt.approx.f32 %0, %1;" : "=f"(r) : "f"(x)); return r;
}

// acos on [0,1]: deg-7 minimax, abs err ~2e-8 (validated rel_err 0.0)
__device__ __forceinline__ float acos_fast(float x) {
    float p = fmaf(x, -0.0012624911f, 0.0066700901f);
    p = fmaf(x, p, -0.0170881256f);
    p = fmaf(x, p,  0.0308918810f);
    p = fmaf(x, p, -0.0501743046f);
    p = fmaf(x, p,  0.0889789874f);
    p = fmaf(x, p, -0.2145988016f);
    p = fmaf(x, p,  1.5707963050f);
    return sqrta(1.0f - x) * p;
}

__global__ __launch_bounds__(256, 4) void fused_loss_kernel(
    const float* __restrict__ qp,
    const float* __restrict__ qt,
    const float* __restrict__ syms,
    float* __restrict__ out)
{
    // Sign-adjusted symmetry splats, packed 2-wide
    __shared__ ulonglong2 s2[SS][2];
    __shared__ float2 wsum[8];
    __shared__ bool amLast;

    const int tid = threadIdx.x;
    if (tid < SS) {
        float a =  syms[tid * 4 + 0];
        float b = -syms[tid * 4 + 1];
        float c = -syms[tid * 4 + 2];
        float d = -syms[tid * 4 + 3];
        s2[tid][0] = make_ulonglong2(pack2(a, a), pack2(b, b));
        s2[tid][1] = make_ulonglong2(pack2(c, c), pack2(d, d));
    }
    __syncthreads();

    const ull NEG1 = pack2(-1.0f, -1.0f);
    const ull EPS2 = pack2(EPSF, EPSF);

    // 4 rows per block, 64 threads per row, 4 pixels per thread (float4)
    const int row = (blockIdx.x << 2) + (tid >> 6);   // row = b*HH + h
    const int t   = tid & 63;
    const int b   = row >> 8;
    const int h   = row & (HH - 1);
    const int base = b * 4 * PS + h * WW + (t << 2);
    const int dh  = (h < HH - 1) ? WW : -WW;          // mirrored edge: |diff| identical
    const bool hasr = (t < 63);

    // ---- per-channel: load + packed gradient term ----
    float4 P[4], T[4];
    float gsum = 0.0f;
#pragma unroll
    for (int c = 0; c < 4; c++) {
        const float* pp = qp + base + c * PS;
        const float* tt = qt + base + c * PS;
        float4 p  = __ldg((const float4*)pp);
        float4 tq = __ldg((const float4*)tt);
        float4 pd = __ldg((const float4*)(pp + dh));
        float4 td = __ldg((const float4*)(tt + dh));
        float pr3 = hasr ? __ldg(pp + 4) : p.z;   // mirrored right edge (|diff| equal)
        float tr3 = hasr ? __ldg(tt + 4) : tq.z;

        // packed pairs: center (aligned), right-shifted, down
        ull pc01 = pack2(p.x, p.y),  pc23 = pack2(p.z, p.w);
        ull pr01 = pack2(p.y, p.z),  pr23 = pack2(p.w, pr3);
        ull pd01 = pack2(pd.x, pd.y), pd23 = pack2(pd.z, pd.w);
        ull tc01 = pack2(tq.x, tq.y), tc23 = pack2(tq.z, tq.w);
        ull trr01 = pack2(tq.y, tq.z), trr23 = pack2(tq.w, tr3);
        ull td01 = pack2(td.x, td.y),  td23 = pack2(td.z, td.w);

        ull gxp01 = fma2(pc01, NEG1, pr01), gxp23 = fma2(pc23, NEG1, pr23);
        ull gyp01 = fma2(pc01, NEG1, pd01), gyp23 = fma2(pc23, NEG1, pd23);
        ull gxt01 = fma2(tc01, NEG1, trr01), gxt23 = fma2(tc23, NEG1, trr23);
        ull gyt01 = fma2(tc01, NEG1, td01),  gyt23 = fma2(tc23, NEG1, td23);

        ull sp01 = fma2(gxp01, gxp01, fma2(gyp01, gyp01, EPS2));
        ull sp23 = fma2(gxp23, gxp23, fma2(gyp23, gyp23, EPS2));
        ull st01 = fma2(gxt01, gxt01, fma2(gyt01, gyt01, EPS2));
        ull st23 = fma2(gxt23, gxt23, fma2(gyt23, gyt23, EPS2));

        float a0, a1, a2, a3, b0, b1, b2, b3;
        unpack2(sp01, a0, a1); unpack2(sp23, a2, a3);
        unpack2(st01, b0, b1); unpack2(st23, b2, b3);
        gsum += fabsf(sqrta(a0) - sqrta(b0));
        gsum += fabsf(sqrta(a1) - sqrta(b1));
        gsum += fabsf(sqrta(a2) - sqrta(b2));
        gsum += fabsf(sqrta(a3) - sqrta(b3));

        P[c] = p; T[c] = tq;
    }

    // ---- per-pair: relative quaternion on RAW quats (scale folded out) ----
    // r(p,t) is bilinear, so r(p/|p|, t/|t|) = r(p,t) * (1/|p|)(1/|t|).
    ull RW[2], RX[2], RY[2], RZ[2];
    float s[4];
#pragma unroll
    for (int j = 0; j < 2; j++) {
        ull A0 = pack2(((const float*)&P[0])[2*j], ((const float*)&P[0])[2*j+1]);
        ull A1 = pack2(((const float*)&P[1])[2*j], ((const float*)&P[1])[2*j+1]);
        ull A2 = pack2(((const float*)&P[2])[2*j], ((const float*)&P[2])[2*j+1]);
        ull A3 = pack2(((const float*)&P[3])[2*j], ((const float*)&P[3])[2*j+1]);
        ull B0 = pack2(((const float*)&T[0])[2*j], ((const float*)&T[0])[2*j+1]);
        ull B1 = pack2(((const float*)&T[1])[2*j], ((const float*)&T[1])[2*j+1]);
        ull B2 = pack2(((const float*)&T[2])[2*j], ((const float*)&T[2])[2*j+1]);
        ull B3 = pack2(((const float*)&T[3])[2*j], ((const float*)&T[3])[2*j+1]);

        ull dp = fma2(A0, A0, fma2(A1, A1, fma2(A2, A2, mul2(A3, A3))));
        ull dt = fma2(B0, B0, fma2(B1, B1, fma2(B2, B2, mul2(B3, B3))));
        float dp0, dp1, dt0, dt1;
        unpack2(dp, dp0, dp1); unpack2(dt, dt0, dt1);
        s[2*j]   = rsqrta(dp0) * rsqrta(dt0);
        s[2*j+1] = rsqrta(dp1) * rsqrta(dt1);

        ull B0n = mul2(B0, NEG1);
        ull B1n = mul2(B1, NEG1);
        ull B2n = mul2(B2, NEG1);
        ull B3n = mul2(B3, NEG1);

        RW[j] = fma2(B0,  A0, fma2(B1,  A1, fma2(B2,  A2, mul2(B3,  A3))));
        RX[j] = fma2(B0n, A1, fma2(B1,  A0, fma2(B2n, A3, mul2(B3,  A2))));
        RY[j] = fma2(B0n, A2, fma2(B1,  A3, fma2(B2,  A0, mul2(B3n, A1))));
        RZ[j] = fma2(B0n, A3, fma2(B1n, A2, fma2(B2,  A1, mul2(B3,  A0))));
    }

    // ---- 24-symmetry max|dot|, packed; |x| folds into FMNMX ----
    float m0 = 0.0f, m1 = 0.0f, m2 = 0.0f, m3 = 0.0f;
#pragma unroll
    for (int sy = 0; sy < SS; sy++) {
        ulonglong2 vab = s2[sy][0];   // {x,x}, {y,y}
        ulonglong2 vcd = s2[sy][1];   // {z,z}, {w,w}
        ull d01 = fma2(RW[0], vab.x, fma2(RX[0], vab.y, fma2(RY[0], vcd.x, mul2(RZ[0], vcd.y))));
        ull d23 = fma2(RW[1], vab.x, fma2(RX[1], vab.y, fma2(RY[1], vcd.x, mul2(RZ[1], vcd.y))));
        float a, bb;
        unpack2(d01, a, bb); m0 = fmaxf(m0, fabsf(a)); m1 = fmaxf(m1, fabsf(bb));
        unpack2(d23, a, bb); m2 = fmaxf(m2, fabsf(a)); m3 = fmaxf(m3, fabsf(bb));
    }
    const float CL = 1.0f - EPSF;
    float rot = acos_fast(fminf(m0 * s[0], CL)) + acos_fast(fminf(m1 * s[1], CL))
              + acos_fast(fminf(m2 * s[2], CL)) + acos_fast(fminf(m3 * s[3], CL));
    rot *= 2.0f;

    // ---- block reduction ----
    float r = rot, g = gsum;
#pragma unroll
    for (int o = 16; o > 0; o >>= 1) {
        r += __shfl_xor_sync(0xFFFFFFFFu, r, o);
        g += __shfl_xor_sync(0xFFFFFFFFu, g, o);
    }
    const int lane = tid & 31;
    const int warp = tid >> 5;
    if (lane == 0) wsum[warp] = make_float2(r, g);
    __syncthreads();
    if (warp == 0) {
        float2 v = (lane < 8) ? wsum[lane] : make_float2(0.0f, 0.0f);
        float rr = v.x, gg = v.y;
#pragma unroll
        for (int o = 4; o > 0; o >>= 1) {
            rr += __shfl_xor_sync(0xFFFFFFFFu, rr, o);
            gg += __shfl_xor_sync(0xFFFFFFFFu, gg, o);
        }
        if (lane == 0) {
            g_partials[blockIdx.x] = make_float2(rr, gg);
            __threadfence();
            unsigned int c = atomicAdd(&g_count, 1u);
            amLast = (c == NBLK - 1);
        }
    }
    __syncthreads();

    // ---- last block: grid-wide finish (deterministic fixed-order sum) ----
    if (amLast) {
        float r2 = 0.0f, g2 = 0.0f;
#pragma unroll
        for (int i = tid; i < NBLK; i += 256) {
            float2 v = __ldcg(&g_partials[i]);
            r2 += v.x; g2 += v.y;
        }
#pragma unroll
        for (int o = 16; o > 0; o >>= 1) {
            r2 += __shfl_xor_sync(0xFFFFFFFFu, r2, o);
            g2 += __shfl_xor_sync(0xFFFFFFFFu, g2, o);
        }
        if (lane == 0) wsum[warp] = make_float2(r2, g2);
        __syncthreads();
        if (tid == 0) {
            float rr = 0.0f, gg = 0.0f;
#pragma unroll
            for (int i = 0; i < 8; i++) { rr += wsum[i].x; gg += wsum[i].y; }
            out[0] = rr / (float)NPIX + WGRAD * (gg / (float)(4 * NPIX));
            g_count = 0;   // reset for next graph replay
        }
    }
}

extern "C" void kernel_launch(void* const* d_in, const int* in_sizes, int n_in,
                              void* d_out, int out_size)
{
    const float* qp   = (const float*)d_in[0];
    const float* qt   = (const float*)d_in[1];
    const float* syms = (const float*)d_in[2];
    float* out = (float*)d_out;

    fused_loss_kernel<<<NBLK, 256>>>(qp, qt, syms, out);
}